// round 17
// baseline (speedup 1.0000x reference)
#include <cuda_runtime.h>
#include <cuda_bf16.h>
#include <math.h>
#include <stdint.h>

#define Bsz 8
#define Lsz 2048
#define Dsz 256
#define NPGC 4
#define NS4 4
#define EPS_T 1.1920929e-07f
#define EPS_C 1e-8f
#define ML (Bsz*Lsz)

typedef __nv_bfloat16 bf16;
typedef __nv_bfloat162 bf162;

// ---------------- scratch (static __device__, no allocs) ----------------
__device__ float g_h [ML*Dsz];
__device__ float g_b1[ML*2*Dsz];
__device__ float g_b2[ML*Dsz];
__device__ float g_b3[ML*Dsz];
__device__ float g_b4[ML*Dsz];
__device__ float g_lam_r[Dsz*32], g_lam_i[Dsz*32], g_cm_r[Dsz*32], g_cm_i[Dsz*32];

__device__ bf16 g_xh[ML*Dsz], g_xl[ML*Dsz];
__device__ bf16 g_yh[ML*Dsz], g_yl[ML*Dsz];
__device__ bf16 g_qh[ML*Dsz], g_ql[ML*Dsz];
__device__ bf16 g_kh[ML*Dsz], g_kl[ML*Dsz];

#define OFF_PIN  0
#define OFF_POUT 524288
#define OFF_S4   786432
#define OFF_Q    1310720
#define OFF_K    1376256
#define OFF_DB   1441792
#define OFF_BIN  1474560
#define WTOT     1490944
__device__ bf16 g_wh[WTOT], g_wl[WTOT];

__device__ __forceinline__ float gelu_f(float x) {
    return 0.5f * x * (1.f + erff(x * 0.70710678118654752f));
}
__device__ __forceinline__ void split2(float v, bf16& h, bf16& l) {
    h = __float2bfloat16_rn(v);
    l = __float2bfloat16_rn(v - __bfloat162float(h));
}
__device__ __forceinline__ void mma_bf16(float* d, const uint32_t* a, const uint32_t* b) {
    asm volatile(
        "mma.sync.aligned.m16n8k16.row.col.f32.bf16.bf16.f32 "
        "{%0,%1,%2,%3},{%4,%5,%6,%7},{%8,%9},{%0,%1,%2,%3};"
        : "+f"(d[0]), "+f"(d[1]), "+f"(d[2]), "+f"(d[3])
        : "r"(a[0]), "r"(a[1]), "r"(a[2]), "r"(a[3]), "r"(b[0]), "r"(b[1]));
}

// ---------------- prep 1/2: batched weight transpose+split ----------------
__global__ void wsplit_b(const float* __restrict__ w, bf16* __restrict__ oh,
                         bf16* __restrict__ ol, int K, int N,
                         long wstride, long ostride) {
    __shared__ float t[32][33];
    int layer = blockIdx.z;
    const float* wp = w + (long)layer * wstride;
    bf16* ohp = oh + (long)layer * ostride;
    bf16* olp = ol + (long)layer * ostride;
    int n0 = blockIdx.x * 32, k0 = blockIdx.y * 32;
    int tx = threadIdx.x, ty = threadIdx.y;
    #pragma unroll
    for (int j = 0; j < 32; j += 8)
        t[ty + j][tx] = wp[(long)(k0 + ty + j) * N + n0 + tx];
    __syncthreads();
    #pragma unroll
    for (int j = 0; j < 32; j += 8) {
        float v = t[tx][ty + j];
        bf16 hh, ll; split2(v, hh, ll);
        long o = (long)(n0 + ty + j) * K + k0 + tx;
        ohp[o] = hh; olp[o] = ll;
    }
}

// ---------------- device helper: one 32x32 transpose+split tile ----------------
__device__ __forceinline__ void tile_tsplit(const float* __restrict__ w, int N,
                                            bf16* __restrict__ oh, bf16* __restrict__ ol,
                                            int n0, int k0) {
    __shared__ float t[32][33];
    int tid = threadIdx.x;
    int r = tid >> 3, c = (tid & 7) * 4;
    #pragma unroll
    for (int j = 0; j < 4; j++)
        t[r][c + j] = w[(long)(k0 + r) * N + n0 + c + j];
    __syncthreads();
    #pragma unroll
    for (int j = 0; j < 4; j++) {
        float v = t[c + j][r];
        bf16 hh, ll; split2(v, hh, ll);
        long o = (long)(n0 + r) * 256 + k0 + c + j;
        oh[o] = hh; ol[o] = ll;
    }
}

// ---------------- prep 3: encoder + misc weight splits ----------------
__global__ void encoder_prep_k(const float* __restrict__ x, const float* __restrict__ w,
                               const float* __restrict__ b, float* __restrict__ h,
                               bf16* __restrict__ oh, bf16* __restrict__ ol,
                               const float* __restrict__ s4_out_w,
                               const float* __restrict__ q_w, const float* __restrict__ k_w,
                               const float* __restrict__ db_w, const float* __restrict__ bin_w,
                               bf16* __restrict__ wh, bf16* __restrict__ wl) {
    long bid = blockIdx.x;
    if (bid < ML) {
        int d = threadIdx.x;
        const float* xr = x + bid * 4;
        float acc = b[d];
        #pragma unroll
        for (int i = 0; i < 4; i++) acc = fmaf(xr[i], w[i * 256 + d], acc);
        h[bid * 256 + d] = acc;
        bf16 hh, ll; split2(acc, hh, ll);
        oh[bid * 256 + d] = hh; ol[bid * 256 + d] = ll;
        return;
    }
    int pb = (int)(bid - ML);
    if (pb < 256) {
        long i0 = (long)pb * 512 + threadIdx.x;
        #pragma unroll
        for (int it = 0; it < 2; it++) {
            long i = i0 + it * 256;
            float4 v = ((const float4*)s4_out_w)[i];
            bf16 h0,l0,h1,l1,h2,l2,h3,l3;
            split2(v.x,h0,l0); split2(v.y,h1,l1); split2(v.z,h2,l2); split2(v.w,h3,l3);
            bf162 a2,b2;
            a2.x=h0; a2.y=h1; b2.x=h2; b2.y=h3;
            ((bf162*)(g_wh + OFF_S4))[i*2] = a2; ((bf162*)(g_wh + OFF_S4))[i*2+1] = b2;
            a2.x=l0; a2.y=l1; b2.x=l2; b2.y=l3;
            ((bf162*)(g_wl + OFF_S4))[i*2] = a2; ((bf162*)(g_wl + OFF_S4))[i*2+1] = b2;
        }
        return;
    }
    pb -= 256;
    if (pb < 64) {
        tile_tsplit(q_w, 256, wh + OFF_Q, wl + OFF_Q, (pb & 7) * 32, (pb >> 3) * 32);
    } else if (pb < 128) {
        pb -= 64;
        tile_tsplit(k_w, 256, wh + OFF_K, wl + OFF_K, (pb & 7) * 32, (pb >> 3) * 32);
    } else if (pb < 160) {
        pb -= 128;
        tile_tsplit(db_w, 128, wh + OFF_DB, wl + OFF_DB, (pb & 3) * 32, (pb >> 2) * 32);
    } else {
        pb -= 160;
        tile_tsplit(bin_w, 64, wh + OFF_BIN, wl + OFF_BIN, (pb & 1) * 32, (pb >> 1) * 32);
    }
}

// ---------------- bf16 3-term split GEMM: 128x64 tile, 4x(64x32) warps, 128 thr ----------------
// A [M,K], B [N,K] pre-split K-major bf16. N multiple of 64, M multiple of 128.
#define TBK 16
#define KP 24
__global__ __launch_bounds__(128, 4)
void gemm_bf(const bf16* __restrict__ Ah_, const bf16* __restrict__ Al_,
             const bf16* __restrict__ Bh_, const bf16* __restrict__ Bl_,
             const float* __restrict__ bias,
             float* __restrict__ C, bf16* __restrict__ Ch, bf16* __restrict__ Cl,
             int M, int N, int K,
             long long As_b, long long Bs_b, long long Cs_b, long long Cs_m,
             float alpha, int act) {
    __shared__ __align__(16) bf16 sAh[128][KP], sAl[128][KP];
    __shared__ __align__(16) bf16 sBh[64][KP],  sBl[64][KP];
    int batch = blockIdx.z;
    const bf16* Ah = Ah_ + (long long)batch * As_b;
    const bf16* Al = Al_ + (long long)batch * As_b;
    const bf16* Bh = Bh_ + (long long)batch * Bs_b;
    const bf16* Bl = Bl_ + (long long)batch * Bs_b;
    int m0 = blockIdx.y * 128, n0 = blockIdx.x * 64;
    int tid = threadIdx.x;
    int w = tid >> 5, lane = tid & 31;
    int wm = (w & 1) * 64, wn = (w >> 1) * 32;
    int gid = lane >> 2, tig = lane & 3;

    float acc[4][4][4];
    #pragma unroll
    for (int i = 0; i < 4; i++)
        #pragma unroll
        for (int j = 0; j < 4; j++)
            #pragma unroll
            for (int r = 0; r < 4; r++) acc[i][j][r] = 0.f;

    long long aro = (long long)(m0 + tid) * K;          // one A row per thread
    int brow = tid >> 1, boff = (tid & 1) * 8;          // B: two threads per row
    int bn = n0 + brow;
    long long bro = (long long)((bn < N) ? bn : 0) * K;

    uint4 rah0, rah1, ral0, ral1, rbh, rbl;
    auto fetch = [&](int kt) {
        int k0 = kt * TBK;
        rah0 = *(const uint4*)(Ah + aro + k0);
        rah1 = *(const uint4*)(Ah + aro + k0 + 8);
        ral0 = *(const uint4*)(Al + aro + k0);
        ral1 = *(const uint4*)(Al + aro + k0 + 8);
        rbh  = *(const uint4*)(Bh + bro + k0 + boff);
        rbl  = *(const uint4*)(Bl + bro + k0 + boff);
    };

    int T = K / TBK;
    fetch(0);
    for (int t = 0; t < T; t++) {
        *(uint4*)&sAh[tid][0] = rah0;
        *(uint4*)&sAh[tid][8] = rah1;
        *(uint4*)&sAl[tid][0] = ral0;
        *(uint4*)&sAl[tid][8] = ral1;
        *(uint4*)&sBh[brow][boff] = rbh;
        *(uint4*)&sBl[brow][boff] = rbl;
        __syncthreads();
        if (t + 1 < T) fetch(t + 1);

        uint32_t bhf[4][2], blf[4][2];
        #pragma unroll
        for (int nf = 0; nf < 4; nf++) {
            int nc = wn + nf * 8 + gid;
            bhf[nf][0] = *(const uint32_t*)&sBh[nc][2 * tig];
            bhf[nf][1] = *(const uint32_t*)&sBh[nc][2 * tig + 8];
            blf[nf][0] = *(const uint32_t*)&sBl[nc][2 * tig];
            blf[nf][1] = *(const uint32_t*)&sBl[nc][2 * tig + 8];
        }
        #pragma unroll
        for (int mf = 0; mf < 4; mf++) {
            int mr = wm + mf * 16 + gid;
            uint32_t ah[4], al[4];
            ah[0] = *(const uint32_t*)&sAh[mr    ][2 * tig];
            ah[1] = *(const uint32_t*)&sAh[mr + 8][2 * tig];
            ah[2] = *(const uint32_t*)&sAh[mr    ][2 * tig + 8];
            ah[3] = *(const uint32_t*)&sAh[mr + 8][2 * tig + 8];
            al[0] = *(const uint32_t*)&sAl[mr    ][2 * tig];
            al[1] = *(const uint32_t*)&sAl[mr + 8][2 * tig];
            al[2] = *(const uint32_t*)&sAl[mr    ][2 * tig + 8];
            al[3] = *(const uint32_t*)&sAl[mr + 8][2 * tig + 8];
            #pragma unroll
            for (int nf = 0; nf < 4; nf++) {
                mma_bf16(acc[mf][nf], ah, blf[nf]);
                mma_bf16(acc[mf][nf], al, bhf[nf]);
                mma_bf16(acc[mf][nf], ah, bhf[nf]);
            }
        }
        __syncthreads();
    }

    // epilogue
    float* Cb = C ? C + (long long)batch * Cs_b : (float*)0;
    #pragma unroll
    for (int mf = 0; mf < 4; mf++) {
        #pragma unroll
        for (int nf = 0; nf < 4; nf++) {
            int col = n0 + wn + nf * 8 + 2 * tig;
            if (col >= N) continue;
            int row0 = m0 + wm + mf * 16 + gid;
            float v[4];
            #pragma unroll
            for (int r = 0; r < 4; r++) {
                float t = acc[mf][nf][r] * alpha;
                if (bias) t += bias[col + (r & 1)];
                if (act == 1) t = gelu_f(t);
                v[r] = t;
            }
            if (Cb) {
                Cb[(long long)row0 * Cs_m + col]           = v[0];
                Cb[(long long)row0 * Cs_m + col + 1]       = v[1];
                Cb[(long long)(row0 + 8) * Cs_m + col]     = v[2];
                Cb[(long long)(row0 + 8) * Cs_m + col + 1] = v[3];
            }
            if (Ch) {
                bf16 h0,l0,h1,l1;
                split2(v[0], h0, l0); split2(v[1], h1, l1);
                bf162 ph; ph.x = h0; ph.y = h1;
                bf162 pl; pl.x = l0; pl.y = l1;
                *(bf162*)&Ch[(long long)row0 * N + col] = ph;
                *(bf162*)&Cl[(long long)row0 * N + col] = pl;
                split2(v[2], h0, l0); split2(v[3], h1, l1);
                ph.x = h0; ph.y = h1; pl.x = l0; pl.y = l1;
                *(bf162*)&Ch[(long long)(row0 + 8) * N + col] = ph;
                *(bf162*)&Cl[(long long)(row0 + 8) * N + col] = pl;
            }
        }
    }
}

// ---------------- fused PGC middle: rmsnorm512 + conv3 + gate + rmsnorm256 + split ----------------
__global__ void pgc_mid_k(const float* __restrict__ xv, const float* __restrict__ inw,
                          const float* __restrict__ cw, const float* __restrict__ cb,
                          const float* __restrict__ nw2,
                          bf16* __restrict__ oh, bf16* __restrict__ ol) {
    long bl = blockIdx.x;
    int l = (int)(bl & (Lsz - 1));
    int t = threadIdx.x;                 // 256
    const float* rc = xv + bl * 512;
    float xc = rc[t], vc = rc[256 + t];
    float xm = 0.f, vm = 0.f, xp = 0.f, vp = 0.f;
    if (l > 0)       { xm = rc[-512 + t]; vm = rc[-256 + t]; }
    if (l < Lsz - 1) { xp = rc[ 512 + t]; vp = rc[ 768 + t]; }

    float s0 = fmaf(vc, vc, xc * xc);
    float s1 = fmaf(vm, vm, xm * xm);
    float s2 = fmaf(vp, vp, xp * xp);
    #pragma unroll
    for (int o = 16; o; o >>= 1) {
        s0 += __shfl_xor_sync(~0u, s0, o);
        s1 += __shfl_xor_sync(~0u, s1, o);
        s2 += __shfl_xor_sync(~0u, s2, o);
    }
    __shared__ float sh0[8], sh1[8], sh2[8], shr[3];
    int wid = t >> 5, lane = t & 31;
    if (lane == 0) { sh0[wid] = s0; sh1[wid] = s1; sh2[wid] = s2; }
    __syncthreads();
    if (wid == 0) {
        float a = (lane < 8) ? sh0[lane] : 0.f;
        float b = (lane < 8) ? sh1[lane] : 0.f;
        float c = (lane < 8) ? sh2[lane] : 0.f;
        #pragma unroll
        for (int o = 4; o; o >>= 1) {
            a += __shfl_xor_sync(~0u, a, o);
            b += __shfl_xor_sync(~0u, b, o);
            c += __shfl_xor_sync(~0u, c, o);
        }
        if (lane == 0) { shr[0] = a; shr[1] = b; shr[2] = c; }
    }
    __syncthreads();
    float sc  = rsqrtf(shr[0] / 512.f + EPS_T);
    float smn = rsqrtf(shr[1] / 512.f + EPS_T);
    float sp  = rsqrtf(shr[2] / 512.f + EPS_T);

    float wA = inw[t];
    float xcn = xc * sc  * wA;
    float vn  = vc * sc  * inw[256 + t];
    float xmn = xm * smn * wA;
    float xpn = xp * sp  * wA;
    float w0 = cw[t * 3], w1 = cw[t * 3 + 1], w2 = cw[t * 3 + 2];
    float conv = fmaf(w0, xmn, fmaf(w1, xcn, fmaf(w2, xpn, cb[t])));
    float g = vn * conv;

    float sg = g * g;
    #pragma unroll
    for (int o = 16; o; o >>= 1) sg += __shfl_xor_sync(~0u, sg, o);
    __syncthreads();
    if (lane == 0) sh0[wid] = sg;
    __syncthreads();
    if (wid == 0) {
        float a = (lane < 8) ? sh0[lane] : 0.f;
        #pragma unroll
        for (int o = 4; o; o >>= 1) a += __shfl_xor_sync(~0u, a, o);
        if (lane == 0) shr[0] = a;
    }
    __syncthreads();
    float s2n = rsqrtf(shr[0] / 256.f + EPS_T);
    float ov = g * s2n * nw2[t];
    bf16 hh, ll; split2(ov, hh, ll);
    oh[bl * 256 + t] = hh;
    ol[bl * 256 + t] = ll;
}

// ---------------- RMSNorm (fp32 out) ----------------
__global__ void rmsnorm_k(const float* __restrict__ in, const float* __restrict__ w,
                          float* __restrict__ out, int ncols, float eps) {
    long row = blockIdx.x;
    const float* r = in + row * (long)ncols;
    float ss = 0.f;
    for (int c = threadIdx.x; c < ncols; c += blockDim.x) { float v = r[c]; ss = fmaf(v, v, ss); }
    #pragma unroll
    for (int o = 16; o; o >>= 1) ss += __shfl_xor_sync(~0u, ss, o);
    __shared__ float sh[32];
    int wid = threadIdx.x >> 5, lane = threadIdx.x & 31;
    if (lane == 0) sh[wid] = ss;
    __syncthreads();
    int nw = blockDim.x >> 5;
    if (wid == 0) {
        ss = (lane < nw) ? sh[lane] : 0.f;
        #pragma unroll
        for (int o = 16; o; o >>= 1) ss += __shfl_xor_sync(~0u, ss, o);
        if (lane == 0) sh[0] = ss;
    }
    __syncthreads();
    float scale = rsqrtf(sh[0] / (float)ncols + eps);
    for (int c = threadIdx.x; c < ncols; c += blockDim.x)
        out[row * (long)ncols + c] = r[c] * scale * w[c];
}

// ---------------- transpose (B,L,D) -> (B,D,L) fp32 ----------------
__global__ void transpose_LD(const float* __restrict__ in, float* __restrict__ out) {
    __shared__ float tile[32][33];
    int b = blockIdx.z;
    int l0 = blockIdx.x * 32, d0 = blockIdx.y * 32;
    #pragma unroll
    for (int j = 0; j < 32; j += 8)
        tile[threadIdx.y + j][threadIdx.x] =
            in[((long)b * Lsz + (l0 + threadIdx.y + j)) * Dsz + d0 + threadIdx.x];
    __syncthreads();
    #pragma unroll
    for (int j = 0; j < 32; j += 8)
        out[((long)b * Dsz + (d0 + threadIdx.y + j)) * Lsz + l0 + threadIdx.x] =
            tile[threadIdx.x][threadIdx.y + j];
}

// ---------------- transpose+split (B,D,L) -> (B,L,D) bf16 hi/lo ----------------
__global__ void tsplit_DL(const float* __restrict__ in, bf16* __restrict__ oh,
                          bf16* __restrict__ ol) {
    __shared__ float tile[32][33];
    int b = blockIdx.z;
    int d0 = blockIdx.x * 32, l0 = blockIdx.y * 32;
    #pragma unroll
    for (int j = 0; j < 32; j += 8)
        tile[threadIdx.y + j][threadIdx.x] =
            in[((long)b * Dsz + (d0 + threadIdx.y + j)) * Lsz + l0 + threadIdx.x];
    __syncthreads();
    #pragma unroll
    for (int j = 0; j < 32; j += 8) {
        float v = tile[threadIdx.x][threadIdx.y + j];
        bf16 hh, ll; split2(v, hh, ll);
        long o = ((long)b * Lsz + (l0 + threadIdx.y + j)) * Dsz + d0 + threadIdx.x;
        oh[o] = hh; ol[o] = ll;
    }
}

// ---------------- S4D parameter precompute ----------------
__global__ void s4_pre_k(const float* __restrict__ C_ri, const float* __restrict__ log_dt,
                         const float* __restrict__ logAr, const float* __restrict__ Aim,
                         float* __restrict__ lam_r, float* __restrict__ lam_i,
                         float* __restrict__ cm_r, float* __restrict__ cm_i) {
    int idx = blockIdx.x * blockDim.x + threadIdx.x;
    if (idx >= Dsz * 32) return;
    int h = idx >> 5;
    float dt = expf(log_dt[h]);
    float Ar = -expf(logAr[idx]);
    float Ai = Aim[idx];
    float dr = Ar * dt, di = Ai * dt;
    float er = expf(dr);
    float lr = er * cosf(di), li = er * sinf(di);
    lam_r[idx] = lr; lam_i[idx] = li;
    float Er = lr - 1.f, Ei = li;
    float den = Ar * Ar + Ai * Ai;
    float qr = (Er * Ar + Ei * Ai) / den;
    float qi = (Ei * Ar - Er * Ai) / den;
    float Cr = C_ri[idx * 2], Ci = C_ri[idx * 2 + 1];
    cm_r[idx] = Cr * qr - Ci * qi;
    cm_i[idx] = Cr * qi + Ci * qr;
}

// ---------------- S4D diagonal recurrence (coalesced) ----------------
__global__ void s4_scan_k(const float* __restrict__ u,
                          const float* __restrict__ lam_r, const float* __restrict__ lam_i,
                          const float* __restrict__ cm_r, const float* __restrict__ cm_i,
                          const float* __restrict__ Dp, float* __restrict__ y) {
    int gw = (blockIdx.x * blockDim.x + threadIdx.x) >> 5;
    int lane = threadIdx.x & 31;
    int b = gw >> 8, h = gw & 255;
    int idx = h * 32 + lane;
    float lr = lam_r[idx], li = lam_i[idx];
    float cr = cm_r[idx],  ci = cm_i[idx];
    float dp = Dp[h];
    const float* up = u + ((long)b * Dsz + h) * Lsz;
    float*       yp = y + ((long)b * Dsz + h) * Lsz;
    float sr = 0.f, si = 0.f;
    #pragma unroll 4
    for (int l = 0; l < Lsz; l++) {
        float uv = __ldg(up + l);
        float nsr = fmaf(lr, sr, fmaf(-li, si, uv));
        float nsi = fmaf(lr, si, li * sr);
        sr = nsr; si = nsi;
        float c = cr * sr - ci * si;
        c += __shfl_xor_sync(~0u, c, 16);
        c += __shfl_xor_sync(~0u, c, 8);
        c += __shfl_xor_sync(~0u, c, 4);
        c += __shfl_xor_sync(~0u, c, 2);
        c += __shfl_xor_sync(~0u, c, 1);
        if (lane == 0) {
            float yv = fmaf(dp, uv, 2.f * c);
            yp[l] = gelu_f(yv);
        }
    }
}

// ---------------- GLU + residual (optional split out) ----------------
__global__ void glu_res_k(const float* __restrict__ z, float* __restrict__ h,
                          bf16* __restrict__ oh, bf16* __restrict__ ol) {
    long idx = (long)blockIdx.x * 256 + threadIdx.x;
    long row = idx >> 8;
    int o = (int)(idx & 255);
    float a = z[row * 512 + o];
    float g = z[row * 512 + 256 + o];
    float nv = h[idx] + a * (1.f / (1.f + expf(-g)));
    h[idx] = nv;
    if (oh) {
        bf16 hh, ll; split2(nv, hh, ll);
        oh[idx] = hh; ol[idx] = ll;
    }
}

// ---------------- small scalar GEMM ----------------
__global__ void gemm_small(const float* __restrict__ A, const float* __restrict__ Bm,
                           const float* __restrict__ bias, float* __restrict__ C,
                           int N, int K, long long Cs_m) {
    long m = blockIdx.x;
    int tid = threadIdx.x;
    const float* Ar = A + m * K;
    __shared__ float red[4][128];
    for (int n = 0; n < N; n++) {
        float s = 0.f;
        for (int k = tid; k < K; k += 128) s = fmaf(Ar[k], Bm[(long)k * N + n], s);
        red[n][tid] = s;
    }
    __syncthreads();
    if (tid < N) {
        float s = 0.f;
        #pragma unroll
        for (int i = 0; i < 128; i++) s += red[tid][i];
        C[m * Cs_m + tid] = s + bias[tid];
    }
}

// ---------------- unpaired column ----------------
__global__ void unpaired_k(const float* __restrict__ ub, float* __restrict__ out) {
    int idx = blockIdx.x * blockDim.x + threadIdx.x;
    out[(long)idx * 2054 + 2053] = ub[0];
}

// ---------------- host ----------------
static void gemm_bf_launch(const bf16* Ah, const bf16* Al, const bf16* Bh, const bf16* Bl,
                           const float* bias, float* C, bf16* Ch, bf16* Cl,
                           int M, int N, int K,
                           long long asb, long long bsb, long long csb, long long csm,
                           float alpha, int act, int batch) {
    dim3 grid((N + 63) / 64, M / 128, batch);
    gemm_bf<<<grid, 128>>>(Ah, Al, Bh, Bl, bias, C, Ch, Cl, M, N, K,
                           asb, bsb, csb, csm, alpha, act);
}

extern "C" void kernel_launch(void* const* d_in, const int* in_sizes, int n_in,
                              void* d_out, int out_size) {
    const float* x          = (const float*)d_in[0];
    const float* enc_w      = (const float*)d_in[1];
    const float* enc_b      = (const float*)d_in[2];
    const float* pgc_in_w   = (const float*)d_in[3];
    const float* pgc_in_b   = (const float*)d_in[4];
    const float* pgc_innorm = (const float*)d_in[5];
    const float* pgc_conv_w = (const float*)d_in[6];
    const float* pgc_conv_b = (const float*)d_in[7];
    const float* pgc_norm_w = (const float*)d_in[8];
    const float* pgc_out_w  = (const float*)d_in[9];
    const float* pgc_out_b  = (const float*)d_in[10];
    const float* s4_norm_w  = (const float*)d_in[11];
    const float* s4_Dp      = (const float*)d_in[12];
    const float* s4_C       = (const float*)d_in[13];
    const float* s4_log_dt  = (const float*)d_in[14];
    const float* s4_logAr   = (const float*)d_in[15];
    const float* s4_Aim     = (const float*)d_in[16];
    const float* s4_out_w   = (const float*)d_in[17];
    const float* s4_out_b   = (const float*)d_in[18];
    const float* db_w1      = (const float*)d_in[19];
    const float* db_b1      = (const float*)d_in[20];
    const float* db_w2      = (const float*)d_in[21];
    const float* db_b2      = (const float*)d_in[22];
    const float* bin_w1     = (const float*)d_in[23];
    const float* bin_b1     = (const float*)d_in[24];
    const float* bin_w2     = (const float*)d_in[25];
    const float* bin_b2     = (const float*)d_in[26];
    const float* q_w        = (const float*)d_in[27];
    const float* q_b        = (const float*)d_in[28];
    const float* k_w        = (const float*)d_in[29];
    const float* k_b        = (const float*)d_in[30];
    const float* ub         = (const float*)d_in[31];
    float* out = (float*)d_out;

    float *h, *b1, *b2, *b3, *b4, *lr, *li, *cr, *ci;
    bf16 *xh, *xl, *yh, *yl, *qh, *ql, *kh, *kl, *wh, *wl;
    cudaGetSymbolAddress((void**)&h,  g_h);
    cudaGetSymbolAddress((void**)&b1, g_b1);
    cudaGetSymbolAddress((void**)&b2, g_b2);
    cudaGetSymbolAddress((void**)&b3, g_b3);
    cudaGetSymbolAddress((void**)&b4, g_b4);
    cudaGetSymbolAddress((void**)&lr, g_lam_r);
    cudaGetSymbolAddress((void**)&li, g_lam_i);
    cudaGetSymbolAddress((void**)&cr, g_cm_r);
    cudaGetSymbolAddress((void**)&ci, g_cm_i);
    cudaGetSymbolAddress((void**)&xh, g_xh);
    cudaGetSymbolAddress((void**)&xl, g_xl);
    cudaGetSymbolAddress((void**)&yh, g_yh);
    cudaGetSymbolAddress((void**)&yl, g_yl);
    cudaGetSymbolAddress((void**)&qh, g_qh);
    cudaGetSymbolAddress((void**)&ql, g_ql);
    cudaGetSymbolAddress((void**)&kh, g_kh);
    cudaGetSymbolAddress((void**)&kl, g_kl);
    cudaGetSymbolAddress((void**)&wh, g_wh);
    cudaGetSymbolAddress((void**)&wl, g_wl);

    // ---- prep: 3 launches (first gemm_bf = launch #4, ncu capture slot) ----
    dim3 tt(32, 8);
    wsplit_b<<<dim3(16, 8, 4), tt>>>(pgc_in_w,  wh + OFF_PIN,  wl + OFF_PIN,  256, 512, 131072, 131072);
    wsplit_b<<<dim3(8, 8, 4),  tt>>>(pgc_out_w, wh + OFF_POUT, wl + OFF_POUT, 256, 256, 65536, 65536);
    encoder_prep_k<<<ML + 432, 256>>>(x, enc_w, enc_b, h, xh, xl,
                                      s4_out_w, q_w, k_w, db_w1, bin_w1, wh, wl);

    // ---- PGC stack ----
    for (int i = 0; i < NPGC; i++) {
        gemm_bf_launch(xh, xl, wh + OFF_PIN + (long)i*131072, wl + OFF_PIN + (long)i*131072,
                       pgc_in_b + i*512, b1, 0, 0, ML, 512, 256, 0, 0, 0, 512, 1.f, 0, 1);
        pgc_mid_k<<<ML, 256>>>(b1, pgc_innorm + i*512, pgc_conv_w + i*768,
                               pgc_conv_b + i*256, pgc_norm_w + i*256, yh, yl);
        gemm_bf_launch(yh, yl, wh + OFF_POUT + (long)i*65536, wl + OFF_POUT + (long)i*65536,
                       pgc_out_b + i*256, h, xh, xl, ML, 256, 256, 0, 0, 0, 256, 1.f, 0, 1);
    }

    // ---- S4D stack ----
    for (int i = 0; i < NS4; i++) {
        s4_pre_k<<<32, 256>>>(s4_C + (long)i*16384, s4_log_dt + i*256,
                              s4_logAr + (long)i*8192, s4_Aim + (long)i*8192,
                              lr, li, cr, ci);
        rmsnorm_k<<<ML, 256>>>(h, s4_norm_w + i*256, b2, 256, EPS_C);
        transpose_LD<<<dim3(Lsz/32, Dsz/32, Bsz), tt>>>(b2, b3);
        s4_scan_k<<<(Bsz * Dsz) / 4, 128>>>(b3, lr, li, cr, ci, s4_Dp + i*256, b4);
        tsplit_DL<<<dim3(Dsz/32, Lsz/32, Bsz), tt>>>(b4, xh, xl);
        gemm_bf_launch(xh, xl, wh + OFF_S4 + (long)i*131072, wl + OFF_S4 + (long)i*131072,
                       s4_out_b + i*512, b1, 0, 0, ML, 512, 256, 0, 0, 0, 512, 1.f, 0, 1);
        bf16* so = (i == NS4 - 1) ? xh : (bf16*)0;
        bf16* sl = (i == NS4 - 1) ? xl : (bf16*)0;
        glu_res_k<<<ML, 256>>>(b1, h, so, sl);
    }

    // ---- heads (xh/xl already hold split of final h from last glu_res) ----
    gemm_bf_launch(xh, xl, wh + OFF_DB, wl + OFF_DB, db_b1, b1, 0, 0,
                   ML, 128, 256, 0, 0, 0, 128, 1.f, 1, 1);
    gemm_small<<<ML, 128>>>(b1, db_w2, db_b2, out, 3, 128, 2054);
    gemm_bf_launch(xh, xl, wh + OFF_BIN, wl + OFF_BIN, bin_b1, b1, 0, 0,
                   ML, 64, 256, 0, 0, 0, 64, 1.f, 1, 1);
    gemm_small<<<ML, 128>>>(b1, bin_w2, bin_b2, out + 3, 2, 64, 2054);
    gemm_bf_launch(xh, xl, wh + OFF_Q, wl + OFF_Q, q_b, 0, qh, ql,
                   ML, 256, 256, 0, 0, 0, 256, 1.f, 0, 1);
    gemm_bf_launch(xh, xl, wh + OFF_K, wl + OFF_K, k_b, 0, kh, kl,
                   ML, 256, 256, 0, 0, 0, 256, 1.f, 0, 1);
    // scores = q @ k^T / 16 -> out[:, :, 5:5+2048], batched
    gemm_bf_launch(qh, ql, kh, kl, 0, out + 5, 0, 0,
                   Lsz, Lsz, 256,
                   (long long)Lsz*256, (long long)Lsz*256, (long long)Lsz*2054, 2054,
                   0.0625f, 0, Bsz);
    unpaired_k<<<ML/256, 256>>>(ub, out);
}